// round 2
// baseline (speedup 1.0000x reference)
#include <cuda_runtime.h>
#include <math.h>

#define BB 2
#define NN 8192
#define KNN 16
#define CIN 32
#define SEG 8
#define SEGLEN (NN/SEG)

// ---------------- scratch (device globals: no allocation allowed) ----------------
__device__ float g_d2p[BB*NN*SEG*KNN];
__device__ int   g_idp[BB*NN*SEG*KNN];
__device__ int   g_idx[BB*NN*KNN];
__device__ float g_feat_t[BB*NN*CIN];

// transposed weights: Wt[in_col * R + out_row]
__device__ float g_mlp1Wt[32*32];
__device__ float g_lse1Wt[10*32];
__device__ float g_lse2Wt[10*32];
__device__ float g_p1c1t[64*8];
__device__ float g_p1c2t[8*64];
__device__ float g_p1wmt[64*32];
__device__ float g_p2c1t[64*8];
__device__ float g_p2c2t[8*64];
__device__ float g_p2wmt[64*64];
__device__ float g_mlp2t[64*128];
__device__ float g_scWt[32*128];

// ---------------- prep: transpose all matvec weights ----------------
__global__ void prep_transpose(
    const float* __restrict__ mlp1_W,
    const float* __restrict__ lse1_W,
    const float* __restrict__ lse2_W,
    const float* __restrict__ p1c1, const float* __restrict__ p1c2, const float* __restrict__ p1wm,
    const float* __restrict__ p2c1, const float* __restrict__ p2c2, const float* __restrict__ p2wm,
    const float* __restrict__ mlp2_W, const float* __restrict__ sc_W)
{
    const float* src = 0; float* dst = 0; int R = 0, C = 0;
    switch (blockIdx.x) {
        case 0:  src = mlp1_W; dst = g_mlp1Wt; R = 32;  C = 32; break;
        case 1:  src = lse1_W; dst = g_lse1Wt; R = 32;  C = 10; break;
        case 2:  src = lse2_W; dst = g_lse2Wt; R = 32;  C = 10; break;
        case 3:  src = p1c1;   dst = g_p1c1t;  R = 8;   C = 64; break;
        case 4:  src = p1c2;   dst = g_p1c2t;  R = 64;  C = 8;  break;
        case 5:  src = p1wm;   dst = g_p1wmt;  R = 32;  C = 64; break;
        case 6:  src = p2c1;   dst = g_p2c1t;  R = 8;   C = 64; break;
        case 7:  src = p2c2;   dst = g_p2c2t;  R = 64;  C = 8;  break;
        case 8:  src = p2wm;   dst = g_p2wmt;  R = 64;  C = 64; break;
        case 9:  src = mlp2_W; dst = g_mlp2t;  R = 128; C = 64; break;
        case 10: src = sc_W;   dst = g_scWt;   R = 128; C = 32; break;
        default: return;
    }
    for (int i = threadIdx.x; i < R*C; i += blockDim.x) {
        int r = i / C, c = i % C;
        dst[c*R + r] = src[i];
    }
}

// ---------------- features (B,C,N) -> (B*N, C) for coalesced warp loads ----------------
__global__ void feat_transpose(const float* __restrict__ f) {
    int gid = blockIdx.x * blockDim.x + threadIdx.x;
    if (gid >= BB*NN*CIN) return;
    int c = gid & 31;
    int p = gid >> 5;           // b*N + n
    int b = p / NN, n = p % NN;
    g_feat_t[gid] = f[((size_t)b*CIN + c)*NN + n];
}

// ---------------- KNN phase 1: per-(query, segment) local top-16 ----------------
__global__ void __launch_bounds__(128) knn_part(const float* __restrict__ coords) {
    int b   = blockIdx.z;
    int seg = blockIdx.y;
    int i   = blockIdx.x * 128 + threadIdx.x;
    const float* cb = coords + (size_t)b*NN*3;
    float qx = cb[i*3+0], qy = cb[i*3+1], qz = cb[i*3+2];
    float qsq = qx*qx + qy*qy + qz*qz;

    float d2l[KNN]; int idl[KNN];
#pragma unroll
    for (int t = 0; t < KNN; t++) { d2l[t] = 3.4e38f; idl[t] = -1; }

    __shared__ float4 s[128];
    int base = seg * SEGLEN;
    for (int cs = 0; cs < SEGLEN; cs += 128) {
        int j = base + cs + threadIdx.x;
        float x = cb[j*3+0], y = cb[j*3+1], z = cb[j*3+2];
        s[threadIdx.x] = make_float4(x, y, z, x*x + y*y + z*z);
        __syncthreads();
#pragma unroll 4
        for (int t = 0; t < 128; t++) {
            float4 c = s[t];
            float dot = qx*c.x + qy*c.y + qz*c.z;
            float d2 = (qsq + c.w) - 2.0f*dot;
            if (d2 < d2l[KNN-1]) {
                d2l[KNN-1] = d2; idl[KNN-1] = base + cs + t;
#pragma unroll
                for (int u = KNN-1; u > 0; --u) {
                    if (d2l[u] < d2l[u-1]) {
                        float tf = d2l[u]; d2l[u] = d2l[u-1]; d2l[u-1] = tf;
                        int ti = idl[u]; idl[u] = idl[u-1]; idl[u-1] = ti;
                    }
                }
            }
        }
        __syncthreads();
    }
    size_t off = (((size_t)b*NN + i)*SEG + seg)*KNN;
#pragma unroll
    for (int t = 0; t < KNN; t++) { g_d2p[off+t] = d2l[t]; g_idp[off+t] = idl[t]; }
}

// ---------------- KNN phase 2: merge 8 sorted lists of 16 ----------------
__global__ void knn_merge() {
    int gid = blockIdx.x * blockDim.x + threadIdx.x;   // b*N + i
    if (gid >= BB*NN) return;
    float d2l[KNN]; int idl[KNN];
#pragma unroll
    for (int t = 0; t < KNN; t++) { d2l[t] = 3.4e38f; idl[t] = -1; }
    size_t off = (size_t)gid * SEG * KNN;
    for (int s = 0; s < SEG; s++) {
        for (int t = 0; t < KNN; t++) {
            float d2 = g_d2p[off + s*KNN + t];
            if (d2 >= d2l[KNN-1]) break;   // lists sorted ascending -> rest also fail
            int j = g_idp[off + s*KNN + t];
            d2l[KNN-1] = d2; idl[KNN-1] = j;
#pragma unroll
            for (int u = KNN-1; u > 0; --u) {
                if (d2l[u] < d2l[u-1]) {
                    float tf = d2l[u]; d2l[u] = d2l[u-1]; d2l[u-1] = tf;
                    int ti = idl[u]; idl[u] = idl[u-1]; idl[u-1] = ti;
                }
            }
        }
    }
#pragma unroll
    for (int t = 0; t < KNN; t++) g_idx[gid*KNN + t] = idl[t];
}

// ---------------- fused per-point pipeline ----------------
__device__ __forceinline__ float sigmoidf_(float x) { return 1.0f / (1.0f + expf(-x)); }

// One LSE (10->32 conv+bn+relu, feature broadcast) + AttentivePooling stage.
// Each lane owns enc channel `lane` (rows 0..31) and broadcast row 32+lane.
__device__ __forceinline__ void stage(
    const float* __restrict__ cat, float featv,
    const float* __restrict__ Wlt, const float* __restrict__ bl,
    const float* __restrict__ gl,  const float* __restrict__ btl,
    const float* __restrict__ Wc1t, const float* __restrict__ Wc2t,
    const float* __restrict__ Ws,
    const float* __restrict__ Wmt, const float* __restrict__ bm,
    const float* __restrict__ gm,  const float* __restrict__ btm,
    float* __restrict__ sA, float* __restrict__ sM,
    float* __restrict__ sH, float* __restrict__ sF,
    float* __restrict__ sOut, int nout, int lane)
{
    const float bns = rsqrtf(1.0f + 1e-5f);
    float w[10];
#pragma unroll
    for (int d = 0; d < 10; d++) w[d] = Wlt[d*32 + lane];
    float bias = bl[lane];
    float scl = gl[lane]*bns, shb = btl[lane];

    float e[16];
    float avg = 0.f, mx = -3.4e38f;
#pragma unroll
    for (int k = 0; k < 16; k++) {
        float acc = bias;
#pragma unroll
        for (int d = 0; d < 10; d++) acc = fmaf(w[d], cat[d*16 + k], acc);
        acc = fmaxf(scl*acc + shb, 0.f);   // relu(bn(conv))
        e[k] = acc;
        avg += acc;
        mx = fmaxf(mx, acc);
    }
    avg *= 0.0625f;
    sA[lane] = avg; sA[32 + lane] = featv;   // broadcast rows: avg==max==value
    sM[lane] = mx;  sM[32 + lane] = featv;
    __syncwarp();

    // channel attention hidden (8 for avg, 8 for max), lanes 0..15
    if (lane < 16) {
        const float* src = (lane < 8) ? sA : sM;
        int j = lane & 7;
        float h = 0.f;
#pragma unroll
        for (int c = 0; c < 64; c++) h = fmaf(Wc1t[c*8 + j], src[c], h);
        sH[lane] = fmaxf(h, 0.f);
    }
    __syncwarp();

    // ch = sigmoid(Wc2 @ (h_avg + h_max))  (Wc2 linear => sum hiddens)
    float a = 0.f, b2 = 0.f;
#pragma unroll
    for (int j = 0; j < 8; j++) {
        float hs = sH[j] + sH[8 + j];
        a  = fmaf(Wc2t[j*64 + lane],      hs, a);
        b2 = fmaf(Wc2t[j*64 + 32 + lane], hs, b2);
    }
    float chA = sigmoidf_(a), chB = sigmoidf_(b2);

    float xf = featv * chB;
    float ws0 = Ws[0], ws1 = Ws[1];
    float fA = 0.f, spsum = 0.f;
#pragma unroll
    for (int k = 0; k < 16; k++) {
        float ek = e[k] * chA;
        float vs = ek + xf;            // partial sum over this lane's 2 channels
        float vm = fmaxf(ek, xf);
#pragma unroll
        for (int off = 16; off > 0; off >>= 1) {
            vs += __shfl_xor_sync(0xffffffffu, vs, off);
            vm = fmaxf(vm, __shfl_xor_sync(0xffffffffu, vm, off));
        }
        float sp = sigmoidf_(ws0 * vs * (1.0f/64.0f) + ws1 * vm);
        fA = fmaf(ek, sp, fA);
        spsum += sp;
    }
    sF[lane]      = fA;
    sF[32 + lane] = xf * spsum;
    __syncwarp();

    // pooled mlp: relu(bn(Wm @ f + bm))
    for (int oi = 0; oi < nout; oi += 32) {
        int oc = oi + lane;
        float acc = bm[oc];
#pragma unroll
        for (int j = 0; j < 64; j++) acc = fmaf(Wmt[j*nout + oc], sF[j], acc);
        sOut[oc] = fmaxf(gm[oc]*bns*acc + btm[oc], 0.f);
    }
    __syncwarp();
}

__global__ void __launch_bounds__(128) fused_kernel(
    const float* __restrict__ coords,
    const float* __restrict__ mlp1_b,
    const float* __restrict__ lse1_b, const float* __restrict__ lse1_g, const float* __restrict__ lse1_bt,
    const float* __restrict__ p1_Ws,  const float* __restrict__ p1_bm,  const float* __restrict__ p1_g, const float* __restrict__ p1_bt,
    const float* __restrict__ lse2_b, const float* __restrict__ lse2_g, const float* __restrict__ lse2_bt,
    const float* __restrict__ p2_Ws,  const float* __restrict__ p2_bm,  const float* __restrict__ p2_g, const float* __restrict__ p2_bt,
    const float* __restrict__ mlp2_b,
    const float* __restrict__ sc_b, const float* __restrict__ sc_g, const float* __restrict__ sc_bt,
    float* __restrict__ out)
{
    __shared__ float sFeat[4][32];
    __shared__ float sCat[4][160];
    __shared__ float sA[4][64], sM[4][64], sH[4][16], sF[4][64], sO[4][64];
    __shared__ float sOutAll[4][128];

    int warp = threadIdx.x >> 5, lane = threadIdx.x & 31;
    int p = blockIdx.x * 4 + warp;          // b*N + n
    int b = p >> 13, n = p & (NN - 1);

    sFeat[warp][lane] = g_feat_t[p*CIN + lane];

    const float* cb = coords + ((size_t)b*NN + n)*3;
    float cx = cb[0], cy = cb[1], cz = cb[2];
    if (lane < 16) {
        int j = g_idx[p*KNN + lane];
        const float* nc = coords + ((size_t)b*NN + j)*3;
        float nx = nc[0], ny = nc[1], nz = nc[2];
        float dx = cx - nx, dy = cy - ny, dz = cz - nz;
        float* cat = sCat[warp];
        cat[0*16+lane] = cx; cat[1*16+lane] = cy; cat[2*16+lane] = cz;
        cat[3*16+lane] = nx; cat[4*16+lane] = ny; cat[5*16+lane] = nz;
        cat[6*16+lane] = dx; cat[7*16+lane] = dy; cat[8*16+lane] = dz;
        cat[9*16+lane] = sqrtf(dx*dx + dy*dy + dz*dz);
    }
    __syncwarp();

    // x1 = leaky_relu(mlp1 @ feat + b, 0.2)
    float x1;
    {
        float acc = mlp1_b[lane];
#pragma unroll
        for (int d = 0; d < 32; d++) acc = fmaf(g_mlp1Wt[d*32 + lane], sFeat[warp][d], acc);
        x1 = acc >= 0.f ? acc : 0.2f*acc;
    }

    stage(sCat[warp], x1, g_lse1Wt, lse1_b, lse1_g, lse1_bt,
          g_p1c1t, g_p1c2t, p1_Ws, g_p1wmt, p1_bm, p1_g, p1_bt,
          sA[warp], sM[warp], sH[warp], sF[warp], sO[warp], 32, lane);
    float o1 = sO[warp][lane];

    stage(sCat[warp], o1, g_lse2Wt, lse2_b, lse2_g, lse2_bt,
          g_p2c1t, g_p2c2t, p2_Ws, g_p2wmt, p2_bm, p2_g, p2_bt,
          sA[warp], sM[warp], sH[warp], sF[warp], sO[warp], 64, lane);

    // final: leaky_relu(mlp2 @ o2 + mlp2_b + bn(sc_W @ feat + sc_b), 0.01)
    const float bns = rsqrtf(1.0f + 1e-5f);
#pragma unroll
    for (int r = 0; r < 4; r++) {
        int oc = r*32 + lane;
        float acc = mlp2_b[oc];
#pragma unroll
        for (int j = 0; j < 64; j++) acc = fmaf(g_mlp2t[j*128 + oc], sO[warp][j], acc);
        float s = sc_b[oc];
#pragma unroll
        for (int d = 0; d < 32; d++) s = fmaf(g_scWt[d*128 + oc], sFeat[warp][d], s);
        acc += sc_g[oc]*bns*s + sc_bt[oc];
        sOutAll[warp][oc] = acc >= 0.f ? acc : 0.01f*acc;
    }
    __syncthreads();

    // coalesced-ish output: thread t writes channel t for the block's 4 points
    int p0 = blockIdx.x * 4;
    int b0 = p0 >> 13, n0 = p0 & (NN - 1);
    float4 v = make_float4(sOutAll[0][threadIdx.x], sOutAll[1][threadIdx.x],
                           sOutAll[2][threadIdx.x], sOutAll[3][threadIdx.x]);
    *reinterpret_cast<float4*>(&out[((size_t)b0*128 + threadIdx.x)*NN + n0]) = v;
}

// ---------------- launch ----------------
extern "C" void kernel_launch(void* const* d_in, const int* in_sizes, int n_in,
                              void* d_out, int out_size) {
    const float* coords   = (const float*)d_in[0];
    const float* features = (const float*)d_in[1];
    const float* mlp1_W = (const float*)d_in[2];
    const float* mlp1_b = (const float*)d_in[3];
    const float* lse1_W = (const float*)d_in[4];
    const float* lse1_b = (const float*)d_in[5];
    const float* lse1_g = (const float*)d_in[6];
    const float* lse1_bt = (const float*)d_in[7];
    const float* p1_Wc1 = (const float*)d_in[8];
    const float* p1_Wc2 = (const float*)d_in[9];
    const float* p1_Ws  = (const float*)d_in[10];
    const float* p1_Wm  = (const float*)d_in[11];
    const float* p1_bm  = (const float*)d_in[12];
    const float* p1_g   = (const float*)d_in[13];
    const float* p1_bt  = (const float*)d_in[14];
    const float* lse2_W = (const float*)d_in[15];
    const float* lse2_b = (const float*)d_in[16];
    const float* lse2_g = (const float*)d_in[17];
    const float* lse2_bt = (const float*)d_in[18];
    const float* p2_Wc1 = (const float*)d_in[19];
    const float* p2_Wc2 = (const float*)d_in[20];
    const float* p2_Ws  = (const float*)d_in[21];
    const float* p2_Wm  = (const float*)d_in[22];
    const float* p2_bm  = (const float*)d_in[23];
    const float* p2_g   = (const float*)d_in[24];
    const float* p2_bt  = (const float*)d_in[25];
    const float* mlp2_W = (const float*)d_in[26];
    const float* mlp2_b = (const float*)d_in[27];
    const float* sc_W   = (const float*)d_in[28];
    const float* sc_b   = (const float*)d_in[29];
    const float* sc_g   = (const float*)d_in[30];
    const float* sc_bt  = (const float*)d_in[31];
    float* out = (float*)d_out;

    prep_transpose<<<11, 256>>>(mlp1_W, lse1_W, lse2_W, p1_Wc1, p1_Wc2, p1_Wm,
                                p2_Wc1, p2_Wc2, p2_Wm, mlp2_W, sc_W);
    feat_transpose<<<(BB*NN*CIN)/256, 256>>>(features);
    knn_part<<<dim3(NN/128, SEG, BB), 128>>>(coords);
    knn_merge<<<(BB*NN)/128, 128>>>();
    fused_kernel<<<(BB*NN)/4, 128>>>(coords, mlp1_b, lse1_b, lse1_g, lse1_bt,
                                     p1_Ws, p1_bm, p1_g, p1_bt,
                                     lse2_b, lse2_g, lse2_bt,
                                     p2_Ws, p2_bm, p2_g, p2_bt,
                                     mlp2_b, sc_b, sc_g, sc_bt, out);
}

// round 3
// speedup vs baseline: 2.1486x; 2.1486x over previous
#include <cuda_runtime.h>
#include <math.h>

#define BB 2
#define NN 8192
#define KNN 16
#define CIN 32
#define FULLW 0xffffffffu

// ---------------- scratch (device globals: no allocation allowed) ----------------
__device__ int   g_idx[BB*NN*KNN];
__device__ float g_feat_t[BB*NN*CIN];

// transposed weights: Wt[in_col * R + out_row]
__device__ float g_mlp1Wt[32*32];
__device__ float g_lse1Wt[10*32];
__device__ float g_lse2Wt[10*32];
__device__ float g_p1c1t[64*8];
__device__ float g_p1c2t[8*64];
__device__ float g_p1wmt[64*32];
__device__ float g_p2c1t[64*8];
__device__ float g_p2c2t[8*64];
__device__ float g_p2wmt[64*64];
__device__ float g_mlp2t[64*128];
__device__ float g_scWt[32*128];

// ---------------- prep: transpose all matvec weights ----------------
__global__ void prep_transpose(
    const float* __restrict__ mlp1_W,
    const float* __restrict__ lse1_W,
    const float* __restrict__ lse2_W,
    const float* __restrict__ p1c1, const float* __restrict__ p1c2, const float* __restrict__ p1wm,
    const float* __restrict__ p2c1, const float* __restrict__ p2c2, const float* __restrict__ p2wm,
    const float* __restrict__ mlp2_W, const float* __restrict__ sc_W)
{
    const float* src = 0; float* dst = 0; int R = 0, C = 0;
    switch (blockIdx.x) {
        case 0:  src = mlp1_W; dst = g_mlp1Wt; R = 32;  C = 32; break;
        case 1:  src = lse1_W; dst = g_lse1Wt; R = 32;  C = 10; break;
        case 2:  src = lse2_W; dst = g_lse2Wt; R = 32;  C = 10; break;
        case 3:  src = p1c1;   dst = g_p1c1t;  R = 8;   C = 64; break;
        case 4:  src = p1c2;   dst = g_p1c2t;  R = 64;  C = 8;  break;
        case 5:  src = p1wm;   dst = g_p1wmt;  R = 32;  C = 64; break;
        case 6:  src = p2c1;   dst = g_p2c1t;  R = 8;   C = 64; break;
        case 7:  src = p2c2;   dst = g_p2c2t;  R = 64;  C = 8;  break;
        case 8:  src = p2wm;   dst = g_p2wmt;  R = 64;  C = 64; break;
        case 9:  src = mlp2_W; dst = g_mlp2t;  R = 128; C = 64; break;
        case 10: src = sc_W;   dst = g_scWt;   R = 128; C = 32; break;
        default: return;
    }
    for (int i = threadIdx.x; i < R*C; i += blockDim.x) {
        int r = i / C, c = i % C;
        dst[c*R + r] = src[i];
    }
}

// ---------------- features (B,C,N) -> (B*N, C) for coalesced warp loads ----------------
__global__ void feat_transpose(const float* __restrict__ f) {
    int gid = blockIdx.x * blockDim.x + threadIdx.x;
    if (gid >= BB*NN*CIN) return;
    int c = gid & 31;
    int p = gid >> 5;           // b*N + n
    int b = p / NN, n = p % NN;
    g_feat_t[gid] = f[((size_t)b*CIN + c)*NN + n];
}

// ---------------- KNN: one warp per query, cooperative distributed top-16 ----------------
// List lives in lanes 0..15 (sorted ascending by (d2', j)); d2' = sq_j - 2*dot (qsq
// omitted: constant per query, fp-add of a constant is monotone so order is preserved).
// Candidates are processed in ascending j; insertion goes AFTER equal values -> exact
// match of jax.lax.top_k stable lowest-index-first tie-break.
#define KQPB 8       // queries (warps) per block
#define KTILE 2048   // candidates staged per tile (32KB shared)

__global__ void __launch_bounds__(256) knn_kernel(const float* __restrict__ coords) {
    __shared__ float4 sc[KTILE];
    int b = blockIdx.y;
    int warp = threadIdx.x >> 5, lane = threadIdx.x & 31;
    int q = blockIdx.x * KQPB + warp;
    const float* cb = coords + (size_t)b*NN*3;
    float qx = cb[q*3+0], qy = cb[q*3+1], qz = cb[q*3+2];

    float lv = 3.4e38f;   // lane's slot of the distributed sorted top-16
    int   li = -1;
    float tau = 3.4e38f;  // current 16th-best (lane 15's value), warp-uniform

    for (int t0 = 0; t0 < NN; t0 += KTILE) {
        __syncthreads();
        // stage tile: (-2x, -2y, -2z, x^2+y^2+z^2)
        for (int u = threadIdx.x; u < KTILE; u += 256) {
            int j = t0 + u;
            float x = cb[j*3+0], y = cb[j*3+1], z = cb[j*3+2];
            sc[u] = make_float4(-2.0f*x, -2.0f*y, -2.0f*z, x*x + y*y + z*z);
        }
        __syncthreads();

        for (int u = 0; u < KTILE; u += 32) {
            float4 c = sc[u + lane];
            float d2 = fmaf(qx, c.x, fmaf(qy, c.y, fmaf(qz, c.z, c.w)));
            int jc = t0 + u + lane;
            unsigned m = __ballot_sync(FULLW, d2 < tau);
            while (m) {
                int src = __ffs(m) - 1;
                m &= m - 1;
                float v  = __shfl_sync(FULLW, d2, src);
                int   vj = __shfl_sync(FULLW, jc, src);
                if (v < tau) {  // warp-uniform (v broadcast, tau uniform)
                    unsigned le = __ballot_sync(FULLW, (lane < KNN) && (lv <= v));
                    int pos = __popc(le);                 // insert position (after equals)
                    float upv = __shfl_up_sync(FULLW, lv, 1);
                    int   upi = __shfl_up_sync(FULLW, li, 1);
                    if (lane == pos)                     { lv = v;   li = vj;  }
                    else if (lane > pos && lane < KNN)   { lv = upv; li = upi; }
                    tau = __shfl_sync(FULLW, lv, KNN-1);
                }
            }
        }
    }
    if (lane < KNN) g_idx[((size_t)b*NN + q)*KNN + lane] = li;
}

// ---------------- fused per-point pipeline ----------------
__device__ __forceinline__ float sigmoidf_(float x) { return 1.0f / (1.0f + expf(-x)); }

// One LSE (10->32 conv+bn+relu, feature broadcast) + AttentivePooling stage.
// Each lane owns enc channel `lane` (rows 0..31) and broadcast row 32+lane.
__device__ __forceinline__ void stage(
    const float* __restrict__ cat, float featv,
    const float* __restrict__ Wlt, const float* __restrict__ bl,
    const float* __restrict__ gl,  const float* __restrict__ btl,
    const float* __restrict__ Wc1t, const float* __restrict__ Wc2t,
    const float* __restrict__ Ws,
    const float* __restrict__ Wmt, const float* __restrict__ bm,
    const float* __restrict__ gm,  const float* __restrict__ btm,
    float* __restrict__ sA, float* __restrict__ sM,
    float* __restrict__ sH, float* __restrict__ sF,
    float* __restrict__ sOut, int nout, int lane)
{
    const float bns = rsqrtf(1.0f + 1e-5f);
    float w[10];
#pragma unroll
    for (int d = 0; d < 10; d++) w[d] = Wlt[d*32 + lane];
    float bias = bl[lane];
    float scl = gl[lane]*bns, shb = btl[lane];

    float e[16];
    float avg = 0.f, mx = -3.4e38f;
#pragma unroll
    for (int k = 0; k < 16; k++) {
        float acc = bias;
#pragma unroll
        for (int d = 0; d < 10; d++) acc = fmaf(w[d], cat[d*16 + k], acc);
        acc = fmaxf(scl*acc + shb, 0.f);   // relu(bn(conv))
        e[k] = acc;
        avg += acc;
        mx = fmaxf(mx, acc);
    }
    avg *= 0.0625f;
    sA[lane] = avg; sA[32 + lane] = featv;   // broadcast rows: avg==max==value
    sM[lane] = mx;  sM[32 + lane] = featv;
    __syncwarp();

    // channel attention hidden (8 for avg, 8 for max), lanes 0..15
    if (lane < 16) {
        const float* src = (lane < 8) ? sA : sM;
        int j = lane & 7;
        float h = 0.f;
#pragma unroll
        for (int c = 0; c < 64; c++) h = fmaf(Wc1t[c*8 + j], src[c], h);
        sH[lane] = fmaxf(h, 0.f);
    }
    __syncwarp();

    // ch = sigmoid(Wc2 @ (h_avg + h_max))  (Wc2 linear => sum hiddens)
    float a = 0.f, b2 = 0.f;
#pragma unroll
    for (int j = 0; j < 8; j++) {
        float hs = sH[j] + sH[8 + j];
        a  = fmaf(Wc2t[j*64 + lane],      hs, a);
        b2 = fmaf(Wc2t[j*64 + 32 + lane], hs, b2);
    }
    float chA = sigmoidf_(a), chB = sigmoidf_(b2);

    float xf = featv * chB;
    float ws0 = Ws[0], ws1 = Ws[1];
    float fA = 0.f, spsum = 0.f;
#pragma unroll
    for (int k = 0; k < 16; k++) {
        float ek = e[k] * chA;
        float vs = ek + xf;            // partial sum over this lane's 2 channels
        float vm = fmaxf(ek, xf);
#pragma unroll
        for (int off = 16; off > 0; off >>= 1) {
            vs += __shfl_xor_sync(0xffffffffu, vs, off);
            vm = fmaxf(vm, __shfl_xor_sync(0xffffffffu, vm, off));
        }
        float sp = sigmoidf_(ws0 * vs * (1.0f/64.0f) + ws1 * vm);
        fA = fmaf(ek, sp, fA);
        spsum += sp;
    }
    sF[lane]      = fA;
    sF[32 + lane] = xf * spsum;
    __syncwarp();

    // pooled mlp: relu(bn(Wm @ f + bm))
    for (int oi = 0; oi < nout; oi += 32) {
        int oc = oi + lane;
        float acc = bm[oc];
#pragma unroll
        for (int j = 0; j < 64; j++) acc = fmaf(Wmt[j*nout + oc], sF[j], acc);
        sOut[oc] = fmaxf(gm[oc]*bns*acc + btm[oc], 0.f);
    }
    __syncwarp();
}

__global__ void __launch_bounds__(128) fused_kernel(
    const float* __restrict__ coords,
    const float* __restrict__ mlp1_b,
    const float* __restrict__ lse1_b, const float* __restrict__ lse1_g, const float* __restrict__ lse1_bt,
    const float* __restrict__ p1_Ws,  const float* __restrict__ p1_bm,  const float* __restrict__ p1_g, const float* __restrict__ p1_bt,
    const float* __restrict__ lse2_b, const float* __restrict__ lse2_g, const float* __restrict__ lse2_bt,
    const float* __restrict__ p2_Ws,  const float* __restrict__ p2_bm,  const float* __restrict__ p2_g, const float* __restrict__ p2_bt,
    const float* __restrict__ mlp2_b,
    const float* __restrict__ sc_b, const float* __restrict__ sc_g, const float* __restrict__ sc_bt,
    float* __restrict__ out)
{
    __shared__ float sFeat[4][32];
    __shared__ float sCat[4][160];
    __shared__ float sA[4][64], sM[4][64], sH[4][16], sF[4][64], sO[4][64];
    __shared__ float sOutAll[4][128];

    int warp = threadIdx.x >> 5, lane = threadIdx.x & 31;
    int p = blockIdx.x * 4 + warp;          // b*N + n
    int b = p >> 13, n = p & (NN - 1);

    sFeat[warp][lane] = g_feat_t[p*CIN + lane];

    const float* cb = coords + ((size_t)b*NN + n)*3;
    float cx = cb[0], cy = cb[1], cz = cb[2];
    if (lane < 16) {
        int j = g_idx[p*KNN + lane];
        const float* nc = coords + ((size_t)b*NN + j)*3;
        float nx = nc[0], ny = nc[1], nz = nc[2];
        float dx = cx - nx, dy = cy - ny, dz = cz - nz;
        float* cat = sCat[warp];
        cat[0*16+lane] = cx; cat[1*16+lane] = cy; cat[2*16+lane] = cz;
        cat[3*16+lane] = nx; cat[4*16+lane] = ny; cat[5*16+lane] = nz;
        cat[6*16+lane] = dx; cat[7*16+lane] = dy; cat[8*16+lane] = dz;
        cat[9*16+lane] = sqrtf(dx*dx + dy*dy + dz*dz);
    }
    __syncwarp();

    // x1 = leaky_relu(mlp1 @ feat + b, 0.2)
    float x1;
    {
        float acc = mlp1_b[lane];
#pragma unroll
        for (int d = 0; d < 32; d++) acc = fmaf(g_mlp1Wt[d*32 + lane], sFeat[warp][d], acc);
        x1 = acc >= 0.f ? acc : 0.2f*acc;
    }

    stage(sCat[warp], x1, g_lse1Wt, lse1_b, lse1_g, lse1_bt,
          g_p1c1t, g_p1c2t, p1_Ws, g_p1wmt, p1_bm, p1_g, p1_bt,
          sA[warp], sM[warp], sH[warp], sF[warp], sO[warp], 32, lane);
    float o1 = sO[warp][lane];

    stage(sCat[warp], o1, g_lse2Wt, lse2_b, lse2_g, lse2_bt,
          g_p2c1t, g_p2c2t, p2_Ws, g_p2wmt, p2_bm, p2_g, p2_bt,
          sA[warp], sM[warp], sH[warp], sF[warp], sO[warp], 64, lane);

    // final: leaky_relu(mlp2 @ o2 + mlp2_b + bn(sc_W @ feat + sc_b), 0.01)
    const float bns = rsqrtf(1.0f + 1e-5f);
#pragma unroll
    for (int r = 0; r < 4; r++) {
        int oc = r*32 + lane;
        float acc = mlp2_b[oc];
#pragma unroll
        for (int j = 0; j < 64; j++) acc = fmaf(g_mlp2t[j*128 + oc], sO[warp][j], acc);
        float s = sc_b[oc];
#pragma unroll
        for (int d = 0; d < 32; d++) s = fmaf(g_scWt[d*128 + oc], sFeat[warp][d], s);
        acc += sc_g[oc]*bns*s + sc_bt[oc];
        sOutAll[warp][oc] = acc >= 0.f ? acc : 0.01f*acc;
    }
    __syncthreads();

    // coalesced-ish output: thread t writes channel t for the block's 4 points
    int p0 = blockIdx.x * 4;
    int b0 = p0 >> 13, n0 = p0 & (NN - 1);
    float4 v = make_float4(sOutAll[0][threadIdx.x], sOutAll[1][threadIdx.x],
                           sOutAll[2][threadIdx.x], sOutAll[3][threadIdx.x]);
    *reinterpret_cast<float4*>(&out[((size_t)b0*128 + threadIdx.x)*NN + n0]) = v;
}

// ---------------- launch ----------------
extern "C" void kernel_launch(void* const* d_in, const int* in_sizes, int n_in,
                              void* d_out, int out_size) {
    const float* coords   = (const float*)d_in[0];
    const float* features = (const float*)d_in[1];
    const float* mlp1_W = (const float*)d_in[2];
    const float* mlp1_b = (const float*)d_in[3];
    const float* lse1_W = (const float*)d_in[4];
    const float* lse1_b = (const float*)d_in[5];
    const float* lse1_g = (const float*)d_in[6];
    const float* lse1_bt = (const float*)d_in[7];
    const float* p1_Wc1 = (const float*)d_in[8];
    const float* p1_Wc2 = (const float*)d_in[9];
    const float* p1_Ws  = (const float*)d_in[10];
    const float* p1_Wm  = (const float*)d_in[11];
    const float* p1_bm  = (const float*)d_in[12];
    const float* p1_g   = (const float*)d_in[13];
    const float* p1_bt  = (const float*)d_in[14];
    const float* lse2_W = (const float*)d_in[15];
    const float* lse2_b = (const float*)d_in[16];
    const float* lse2_g = (const float*)d_in[17];
    const float* lse2_bt = (const float*)d_in[18];
    const float* p2_Wc1 = (const float*)d_in[19];
    const float* p2_Wc2 = (const float*)d_in[20];
    const float* p2_Ws  = (const float*)d_in[21];
    const float* p2_Wm  = (const float*)d_in[22];
    const float* p2_bm  = (const float*)d_in[23];
    const float* p2_g   = (const float*)d_in[24];
    const float* p2_bt  = (const float*)d_in[25];
    const float* mlp2_W = (const float*)d_in[26];
    const float* mlp2_b = (const float*)d_in[27];
    const float* sc_W   = (const float*)d_in[28];
    const float* sc_b   = (const float*)d_in[29];
    const float* sc_g   = (const float*)d_in[30];
    const float* sc_bt  = (const float*)d_in[31];
    float* out = (float*)d_out;

    prep_transpose<<<11, 256>>>(mlp1_W, lse1_W, lse2_W, p1_Wc1, p1_Wc2, p1_Wm,
                                p2_Wc1, p2_Wc2, p2_Wm, mlp2_W, sc_W);
    feat_transpose<<<(BB*NN*CIN)/256, 256>>>(features);
    knn_kernel<<<dim3(NN/KQPB, BB), 256>>>(coords);
    fused_kernel<<<(BB*NN)/4, 128>>>(coords, mlp1_b, lse1_b, lse1_g, lse1_bt,
                                     p1_Ws, p1_bm, p1_g, p1_bt,
                                     lse2_b, lse2_g, lse2_bt,
                                     p2_Ws, p2_bm, p2_g, p2_bt,
                                     mlp2_b, sc_b, sc_g, sc_bt, out);
}

// round 4
// speedup vs baseline: 2.7282x; 1.2697x over previous
#include <cuda_runtime.h>
#include <math.h>

#define BB 2
#define NN 8192
#define KNN 16
#define CIN 32
#define FULLW 0xffffffffu

// ---------------- scratch (device globals: no allocation allowed) ----------------
__device__ int   g_idx[BB*NN*KNN];
__device__ float g_feat_t[BB*NN*CIN];

// transposed weights: Wt[in_col * R + out_row]
__device__ float g_mlp1Wt[32*32];
__device__ float g_lse1Wt[10*32];
__device__ float g_lse2Wt[10*32];
__device__ float g_p1c1t[64*8];
__device__ float g_p1c2t[8*64];
__device__ float g_p1wmt[64*32];
__device__ float g_p2c1t[64*8];
__device__ float g_p2c2t[8*64];
__device__ float g_p2wmt[64*64];
__device__ float g_mlp2t[64*128];
__device__ float g_scWt[32*128];

// ---------------- prep: transpose all matvec weights ----------------
__global__ void prep_transpose(
    const float* __restrict__ mlp1_W,
    const float* __restrict__ lse1_W,
    const float* __restrict__ lse2_W,
    const float* __restrict__ p1c1, const float* __restrict__ p1c2, const float* __restrict__ p1wm,
    const float* __restrict__ p2c1, const float* __restrict__ p2c2, const float* __restrict__ p2wm,
    const float* __restrict__ mlp2_W, const float* __restrict__ sc_W)
{
    const float* src = 0; float* dst = 0; int R = 0, C = 0;
    switch (blockIdx.x) {
        case 0:  src = mlp1_W; dst = g_mlp1Wt; R = 32;  C = 32; break;
        case 1:  src = lse1_W; dst = g_lse1Wt; R = 32;  C = 10; break;
        case 2:  src = lse2_W; dst = g_lse2Wt; R = 32;  C = 10; break;
        case 3:  src = p1c1;   dst = g_p1c1t;  R = 8;   C = 64; break;
        case 4:  src = p1c2;   dst = g_p1c2t;  R = 64;  C = 8;  break;
        case 5:  src = p1wm;   dst = g_p1wmt;  R = 32;  C = 64; break;
        case 6:  src = p2c1;   dst = g_p2c1t;  R = 8;   C = 64; break;
        case 7:  src = p2c2;   dst = g_p2c2t;  R = 64;  C = 8;  break;
        case 8:  src = p2wm;   dst = g_p2wmt;  R = 64;  C = 64; break;
        case 9:  src = mlp2_W; dst = g_mlp2t;  R = 128; C = 64; break;
        case 10: src = sc_W;   dst = g_scWt;   R = 128; C = 32; break;
        default: return;
    }
    for (int i = threadIdx.x; i < R*C; i += blockDim.x) {
        int r = i / C, c = i % C;
        dst[c*R + r] = src[i];
    }
}

// ---------------- features (B,C,N) -> (B*N, C) ----------------
__global__ void feat_transpose(const float* __restrict__ f) {
    int gid = blockIdx.x * blockDim.x + threadIdx.x;
    if (gid >= BB*NN*CIN) return;
    int c = gid & 31;
    int p = gid >> 5;
    int b = p / NN, n = p % NN;
    g_feat_t[gid] = f[((size_t)b*CIN + c)*NN + n];
}

// ---------------- KNN: one warp per 2 queries, cooperative distributed top-16 ----------------
#define KTILE 2048

__device__ __forceinline__ void insert_pass(unsigned m, float d2, int jc,
                                            float& lv, int& li, float& tau, int lane) {
    while (m) {
        int src = __ffs(m) - 1;
        m &= m - 1;
        float v  = __shfl_sync(FULLW, d2, src);
        int   vj = __shfl_sync(FULLW, jc, src);
        if (v < tau) {
            unsigned le = __ballot_sync(FULLW, (lane < KNN) && (lv <= v));
            int pos = __popc(le);
            float upv = __shfl_up_sync(FULLW, lv, 1);
            int   upi = __shfl_up_sync(FULLW, li, 1);
            if (lane == pos)                   { lv = v;   li = vj;  }
            else if (lane > pos && lane < KNN) { lv = upv; li = upi; }
            tau = __shfl_sync(FULLW, lv, KNN-1);
        }
    }
}

__global__ void __launch_bounds__(256) knn_kernel(const float* __restrict__ coords) {
    __shared__ float4 sc[KTILE];
    int b = blockIdx.y;
    int warp = threadIdx.x >> 5, lane = threadIdx.x & 31;
    int q0 = (blockIdx.x * 8 + warp) * 2;
    int q1 = q0 + 1;
    const float* cb = coords + (size_t)b*NN*3;
    float qx0 = cb[q0*3+0], qy0 = cb[q0*3+1], qz0 = cb[q0*3+2];
    float qx1 = cb[q1*3+0], qy1 = cb[q1*3+1], qz1 = cb[q1*3+2];

    float lv0 = 3.4e38f, lv1 = 3.4e38f;
    int   li0 = -1,      li1 = -1;
    float tau0 = 3.4e38f, tau1 = 3.4e38f;

    for (int t0 = 0; t0 < NN; t0 += KTILE) {
        __syncthreads();
        for (int u = threadIdx.x; u < KTILE; u += 256) {
            int j = t0 + u;
            float x = cb[j*3+0], y = cb[j*3+1], z = cb[j*3+2];
            sc[u] = make_float4(-2.0f*x, -2.0f*y, -2.0f*z, x*x + y*y + z*z);
        }
        __syncthreads();

        for (int u = 0; u < KTILE; u += 32) {
            float4 c = sc[u + lane];
            int jc = t0 + u + lane;
            float d20 = fmaf(qx0, c.x, fmaf(qy0, c.y, fmaf(qz0, c.z, c.w)));
            float d21 = fmaf(qx1, c.x, fmaf(qy1, c.y, fmaf(qz1, c.z, c.w)));
            unsigned m0 = __ballot_sync(FULLW, d20 < tau0);
            insert_pass(m0, d20, jc, lv0, li0, tau0, lane);
            unsigned m1 = __ballot_sync(FULLW, d21 < tau1);
            insert_pass(m1, d21, jc, lv1, li1, tau1, lane);
        }
    }
    if (lane < KNN) {
        g_idx[((size_t)b*NN + q0)*KNN + lane] = li0;
        g_idx[((size_t)b*NN + q1)*KNN + lane] = li1;
    }
}

// ---------------- fused per-point pipeline ----------------
__device__ __forceinline__ float sigmoidf_(float x) { return 1.0f / (1.0f + expf(-x)); }

// LSE (10->32 conv+bn+relu) + AttentivePooling. Lane = channel (0..31 enc, 32+lane bcast).
// Pooled matvec runs block-cooperatively over the block's 4 points (float4 activations).
template<int NOUT>
__device__ __forceinline__ void stage(
    const float* __restrict__ cat, float featv,
    const float* __restrict__ Wlt, const float* __restrict__ bl,
    const float* __restrict__ gl,  const float* __restrict__ btl,
    const float* __restrict__ Wc1t, const float* __restrict__ Wc2t,
    const float* __restrict__ Ws,
    const float* __restrict__ Wmt, const float* __restrict__ bm,
    const float* __restrict__ gm,  const float* __restrict__ btm,
    float* __restrict__ sA, float* __restrict__ sM, float* __restrict__ sH,
    float* __restrict__ sSp,
    float* __restrict__ sF4, float* __restrict__ sPart, float* __restrict__ sOut4,
    int lane, int warp)
{
    const float bns = rsqrtf(1.0f + 1e-5f);
    float w[10];
#pragma unroll
    for (int d = 0; d < 10; d++) w[d] = Wlt[d*32 + lane];
    float bias = bl[lane];
    float scl = gl[lane]*bns, shb = btl[lane];

    float e[16];
    float avg = 0.f, mx = -3.4e38f;
#pragma unroll
    for (int k = 0; k < 16; k++) {
        const float4 c0 = *reinterpret_cast<const float4*>(&cat[k*12 + 0]);
        const float4 c1 = *reinterpret_cast<const float4*>(&cat[k*12 + 4]);
        const float2 c2 = *reinterpret_cast<const float2*>(&cat[k*12 + 8]);
        float acc = bias;
        acc = fmaf(w[0], c0.x, acc); acc = fmaf(w[1], c0.y, acc);
        acc = fmaf(w[2], c0.z, acc); acc = fmaf(w[3], c0.w, acc);
        acc = fmaf(w[4], c1.x, acc); acc = fmaf(w[5], c1.y, acc);
        acc = fmaf(w[6], c1.z, acc); acc = fmaf(w[7], c1.w, acc);
        acc = fmaf(w[8], c2.x, acc); acc = fmaf(w[9], c2.y, acc);
        acc = fmaxf(scl*acc + shb, 0.f);
        e[k] = acc;
        avg += acc;
        mx = fmaxf(mx, acc);
    }
    avg *= 0.0625f;
    sA[lane] = avg; sA[32 + lane] = featv;
    sM[lane] = mx;  sM[32 + lane] = featv;
    __syncwarp();

    // channel attention hidden: full warp (j, src, c-half)
    {
        int j = lane & 7;
        const float* src = ((lane >> 3) & 1) ? sM : sA;
        int c0 = (lane & 16) << 1;   // 0 or 32
        float h = 0.f;
#pragma unroll
        for (int c = 0; c < 32; c++) h = fmaf(Wc1t[(c0 + c)*8 + j], src[c0 + c], h);
        h += __shfl_xor_sync(FULLW, h, 16);
        if (lane < 16) sH[lane] = fmaxf(h, 0.f);
    }
    __syncwarp();

    float a = 0.f, b2 = 0.f;
#pragma unroll
    for (int j = 0; j < 8; j++) {
        float hs = sH[j] + sH[8 + j];
        a  = fmaf(Wc2t[j*64 + lane],      hs, a);
        b2 = fmaf(Wc2t[j*64 + 32 + lane], hs, b2);
    }
    float chA = sigmoidf_(a), chB = sigmoidf_(b2);
    float xf = featv * chB;

    // spatial attention: butterfly reduce-scatter of 16-vector over 32 lanes
    float vs[16], vm[16];
#pragma unroll
    for (int k = 0; k < 16; k++) {
        float ek = e[k] * chA;
        e[k] = ek;
        vs[k] = ek + xf;
        vm[k] = fmaxf(ek, xf);
    }
    // step m=16: 16->8
    {
        bool up = (lane & 16);
#pragma unroll
        for (int i = 0; i < 8; i++) {
            float ss = up ? vs[i] : vs[i+8];
            float ks = up ? vs[i+8] : vs[i];
            vs[i] = ks + __shfl_xor_sync(FULLW, ss, 16);
            float sm2 = up ? vm[i] : vm[i+8];
            float km = up ? vm[i+8] : vm[i];
            vm[i] = fmaxf(km, __shfl_xor_sync(FULLW, sm2, 16));
        }
    }
    {
        bool up = (lane & 8);
#pragma unroll
        for (int i = 0; i < 4; i++) {
            float ss = up ? vs[i] : vs[i+4];
            float ks = up ? vs[i+4] : vs[i];
            vs[i] = ks + __shfl_xor_sync(FULLW, ss, 8);
            float sm2 = up ? vm[i] : vm[i+4];
            float km = up ? vm[i+4] : vm[i];
            vm[i] = fmaxf(km, __shfl_xor_sync(FULLW, sm2, 8));
        }
    }
    {
        bool up = (lane & 4);
#pragma unroll
        for (int i = 0; i < 2; i++) {
            float ss = up ? vs[i] : vs[i+2];
            float ks = up ? vs[i+2] : vs[i];
            vs[i] = ks + __shfl_xor_sync(FULLW, ss, 4);
            float sm2 = up ? vm[i] : vm[i+2];
            float km = up ? vm[i+2] : vm[i];
            vm[i] = fmaxf(km, __shfl_xor_sync(FULLW, sm2, 4));
        }
    }
    {
        bool up = (lane & 2);
        float ss = up ? vs[0] : vs[1];
        float ks = up ? vs[1] : vs[0];
        vs[0] = ks + __shfl_xor_sync(FULLW, ss, 2);
        float sm2 = up ? vm[0] : vm[1];
        float km = up ? vm[1] : vm[0];
        vm[0] = fmaxf(km, __shfl_xor_sync(FULLW, sm2, 2));
    }
    vs[0] += __shfl_xor_sync(FULLW, vs[0], 1);
    vm[0] = fmaxf(vm[0], __shfl_xor_sync(FULLW, vm[0], 1));

    float ws0 = Ws[0], ws1 = Ws[1];
    float sp = sigmoidf_(ws0 * vs[0] * (1.0f/64.0f) + ws1 * vm[0]);
    int kL = (((lane>>4)&1)<<3) | (((lane>>3)&1)<<2) | (((lane>>2)&1)<<1) | ((lane>>1)&1);
    if (!(lane & 1)) sSp[kL] = sp;
    // sum of sp over 16 k (each duplicated twice across warp)
    float sps = sp;
#pragma unroll
    for (int off = 16; off > 0; off >>= 1) sps += __shfl_xor_sync(FULLW, sps, off);
    sps *= 0.5f;
    __syncwarp();

    float fA = 0.f;
#pragma unroll
    for (int k = 0; k < 16; k++) fA = fmaf(e[k], sSp[k], fA);

    sF4[lane*4 + warp]        = fA;
    sF4[(32 + lane)*4 + warp] = xf * sps;
    __syncthreads();

    // cooperative pooled mlp: warp handles j in [warp*16, warp*16+16)
    {
        int jb = warp * 16;
        float acc[NOUT/32][4];
#pragma unroll
        for (int g = 0; g < NOUT/32; g++)
#pragma unroll
            for (int p = 0; p < 4; p++) acc[g][p] = 0.f;
#pragma unroll
        for (int jj = 0; jj < 16; jj++) {
            int j = jb + jj;
            float4 a4 = *reinterpret_cast<const float4*>(&sF4[j*4]);
#pragma unroll
            for (int g = 0; g < NOUT/32; g++) {
                float wv = Wmt[j*NOUT + g*32 + lane];
                acc[g][0] = fmaf(wv, a4.x, acc[g][0]);
                acc[g][1] = fmaf(wv, a4.y, acc[g][1]);
                acc[g][2] = fmaf(wv, a4.z, acc[g][2]);
                acc[g][3] = fmaf(wv, a4.w, acc[g][3]);
            }
        }
#pragma unroll
        for (int g = 0; g < NOUT/32; g++) {
            int oc = g*32 + lane;
            *reinterpret_cast<float4*>(&sPart[(warp*NOUT + oc)*4]) =
                make_float4(acc[g][0], acc[g][1], acc[g][2], acc[g][3]);
        }
    }
    __syncthreads();

    // combine partials -> relu(bn(.)) -> sOut4[oc*4+p]
    {
        int t = warp*32 + lane;
#pragma unroll
        for (int g = 0; g < NOUT/32; g++) {
            int idx = g*128 + t;            // < NOUT*4
            int oc = idx >> 2;
            float s = sPart[(0*NOUT)*4 + idx] + sPart[(1*NOUT)*4 + idx]
                    + sPart[(2*NOUT)*4 + idx] + sPart[(3*NOUT)*4 + idx];
            s += bm[oc];
            sOut4[idx] = fmaxf(gm[oc]*bns*s + btm[oc], 0.f);
        }
    }
    __syncthreads();
}

__global__ void __launch_bounds__(128) fused_kernel(
    const float* __restrict__ coords,
    const float* __restrict__ mlp1_b,
    const float* __restrict__ lse1_b, const float* __restrict__ lse1_g, const float* __restrict__ lse1_bt,
    const float* __restrict__ p1_Ws,  const float* __restrict__ p1_bm,  const float* __restrict__ p1_g, const float* __restrict__ p1_bt,
    const float* __restrict__ lse2_b, const float* __restrict__ lse2_g, const float* __restrict__ lse2_bt,
    const float* __restrict__ p2_Ws,  const float* __restrict__ p2_bm,  const float* __restrict__ p2_g, const float* __restrict__ p2_bt,
    const float* __restrict__ mlp2_b,
    const float* __restrict__ sc_b, const float* __restrict__ sc_g, const float* __restrict__ sc_bt,
    float* __restrict__ out)
{
    __shared__ float sCat[4][192];
    __shared__ float sA[4][64], sM[4][64], sH[4][16], sSp[4][16];
    __shared__ float sFe4[32*4];
    __shared__ float sF4[64*4];
    __shared__ float sPart[4*64*4];
    __shared__ float sOut4[64*4];

    int warp = threadIdx.x >> 5, lane = threadIdx.x & 31;
    int p = blockIdx.x * 4 + warp;
    int b = p >> 13, n = p & (NN - 1);

    sFe4[lane*4 + warp] = g_feat_t[p*CIN + lane];

    const float* cb = coords + ((size_t)b*NN + n)*3;
    float cx = cb[0], cy = cb[1], cz = cb[2];
    if (lane < 16) {
        int j = g_idx[p*KNN + lane];
        const float* nc = coords + ((size_t)b*NN + j)*3;
        float nx = nc[0], ny = nc[1], nz = nc[2];
        float dx = cx - nx, dy = cy - ny, dz = cz - nz;
        float* cat = &sCat[warp][lane*12];
        cat[0] = cx; cat[1] = cy; cat[2] = cz;
        cat[3] = nx; cat[4] = ny; cat[5] = nz;
        cat[6] = dx; cat[7] = dy; cat[8] = dz;
        cat[9] = sqrtf(dx*dx + dy*dy + dz*dz);
    }
    __syncwarp();

    // x1 = leaky_relu(mlp1 @ feat + b, 0.2)
    float x1;
    {
        float acc = mlp1_b[lane];
#pragma unroll
        for (int d = 0; d < 32; d++) acc = fmaf(g_mlp1Wt[d*32 + lane], sFe4[d*4 + warp], acc);
        x1 = acc >= 0.f ? acc : 0.2f*acc;
    }

    stage<32>(sCat[warp], x1, g_lse1Wt, lse1_b, lse1_g, lse1_bt,
              g_p1c1t, g_p1c2t, p1_Ws, g_p1wmt, p1_bm, p1_g, p1_bt,
              sA[warp], sM[warp], sH[warp], sSp[warp],
              sF4, sPart, sOut4, lane, warp);
    float o1 = sOut4[lane*4 + warp];

    stage<64>(sCat[warp], o1, g_lse2Wt, lse2_b, lse2_g, lse2_bt,
              g_p2c1t, g_p2c2t, p2_Ws, g_p2wmt, p2_bm, p2_g, p2_bt,
              sA[warp], sM[warp], sH[warp], sSp[warp],
              sF4, sPart, sOut4, lane, warp);

    // final: leaky_relu(mlp2 @ o2 + mlp2_b + bn(sc_W @ feat + sc_b), 0.01)
    // cooperative: thread (warp,lane) owns oc = warp*32+lane for all 4 points
    const float bns = rsqrtf(1.0f + 1e-5f);
    int oc = warp*32 + lane;
    float a0 = 0.f, a1 = 0.f, a2 = 0.f, a3 = 0.f;
#pragma unroll
    for (int j = 0; j < 64; j++) {
        float4 v = *reinterpret_cast<const float4*>(&sOut4[j*4]);
        float wv = g_mlp2t[j*128 + oc];
        a0 = fmaf(wv, v.x, a0); a1 = fmaf(wv, v.y, a1);
        a2 = fmaf(wv, v.z, a2); a3 = fmaf(wv, v.w, a3);
    }
    float s0 = 0.f, s1 = 0.f, s2 = 0.f, s3 = 0.f;
#pragma unroll
    for (int d = 0; d < 32; d++) {
        float4 f = *reinterpret_cast<const float4*>(&sFe4[d*4]);
        float wv = g_scWt[d*128 + oc];
        s0 = fmaf(wv, f.x, s0); s1 = fmaf(wv, f.y, s1);
        s2 = fmaf(wv, f.z, s2); s3 = fmaf(wv, f.w, s3);
    }
    float gg = sc_g[oc]*bns;
    float base = mlp2_b[oc] + gg*sc_b[oc] + sc_bt[oc];
    float v0 = a0 + gg*s0 + base;
    float v1 = a1 + gg*s1 + base;
    float v2 = a2 + gg*s2 + base;
    float v3 = a3 + gg*s3 + base;
    v0 = v0 >= 0.f ? v0 : 0.01f*v0;
    v1 = v1 >= 0.f ? v1 : 0.01f*v1;
    v2 = v2 >= 0.f ? v2 : 0.01f*v2;
    v3 = v3 >= 0.f ? v3 : 0.01f*v3;

    int p0 = blockIdx.x * 4;
    int b0 = p0 >> 13, n0 = p0 & (NN - 1);
    *reinterpret_cast<float4*>(&out[((size_t)(b0*128 + oc))*NN + n0]) =
        make_float4(v0, v1, v2, v3);
}

// ---------------- launch ----------------
extern "C" void kernel_launch(void* const* d_in, const int* in_sizes, int n_in,
                              void* d_out, int out_size) {
    const float* coords   = (const float*)d_in[0];
    const float* features = (const float*)d_in[1];
    const float* mlp1_W = (const float*)d_in[2];
    const float* mlp1_b = (const float*)d_in[3];
    const float* lse1_W = (const float*)d_in[4];
    const float* lse1_b = (const float*)d_in[5];
    const float* lse1_g = (const float*)d_in[6];
    const float* lse1_bt = (const float*)d_in[7];
    const float* p1_Wc1 = (const float*)d_in[8];
    const float* p1_Wc2 = (const float*)d_in[9];
    const float* p1_Ws  = (const float*)d_in[10];
    const float* p1_Wm  = (const float*)d_in[11];
    const float* p1_bm  = (const float*)d_in[12];
    const float* p1_g   = (const float*)d_in[13];
    const float* p1_bt  = (const float*)d_in[14];
    const float* lse2_W = (const float*)d_in[15];
    const float* lse2_b = (const float*)d_in[16];
    const float* lse2_g = (const float*)d_in[17];
    const float* lse2_bt = (const float*)d_in[18];
    const float* p2_Wc1 = (const float*)d_in[19];
    const float* p2_Wc2 = (const float*)d_in[20];
    const float* p2_Ws  = (const float*)d_in[21];
    const float* p2_Wm  = (const float*)d_in[22];
    const float* p2_bm  = (const float*)d_in[23];
    const float* p2_g   = (const float*)d_in[24];
    const float* p2_bt  = (const float*)d_in[25];
    const float* mlp2_W = (const float*)d_in[26];
    const float* mlp2_b = (const float*)d_in[27];
    const float* sc_W   = (const float*)d_in[28];
    const float* sc_b   = (const float*)d_in[29];
    const float* sc_g   = (const float*)d_in[30];
    const float* sc_bt  = (const float*)d_in[31];
    float* out = (float*)d_out;

    prep_transpose<<<11, 256>>>(mlp1_W, lse1_W, lse2_W, p1_Wc1, p1_Wc2, p1_Wm,
                                p2_Wc1, p2_Wc2, p2_Wm, mlp2_W, sc_W);
    feat_transpose<<<(BB*NN*CIN)/256, 256>>>(features);
    knn_kernel<<<dim3(NN/16, BB), 256>>>(coords);
    fused_kernel<<<(BB*NN)/4, 128>>>(coords, mlp1_b, lse1_b, lse1_g, lse1_bt,
                                     p1_Ws, p1_bm, p1_g, p1_bt,
                                     lse2_b, lse2_g, lse2_bt,
                                     p2_Ws, p2_bm, p2_g, p2_bt,
                                     mlp2_b, sc_b, sc_g, sc_bt, out);
}

// round 5
// speedup vs baseline: 2.9418x; 1.0783x over previous
#include <cuda_runtime.h>
#include <math.h>

#define BB 2
#define NN 8192
#define KNN 16
#define CIN 32
#define FULLW 0xffffffffu

// ---------------- scratch ----------------
__device__ int   g_idx[BB*NN*KNN];
__device__ float g_feat_t[BB*NN*CIN];

// weights, repacked by prep
__device__ float g_mlp1Wt[32*32];    // [d][oc]
__device__ float g_lse1We[3*32];     // (Wext+Wdiff) [d][oc]
__device__ float g_lse1Wn[4*32];     // (Wnb-Wdiff, wdist) [d][oc]
__device__ float g_lse2We[3*32];
__device__ float g_lse2Wn[4*32];
__device__ float g_p1c1p[512];       // [(c>>2)*8 + j]*4 + (c&3)
__device__ float g_p1c2p[512];       // [(c>>2)*64 + oc]*4 + (c&3)
__device__ float g_p1wmt[64*32];     // [j][oc]
__device__ float g_p2c1p[512];
__device__ float g_p2c2p[512];
__device__ float g_p2wmt[64*64];
__device__ float g_mlp2t[64*128];    // [j][oc]
__device__ float g_scWt[32*128];     // [d][oc], pre-scaled by sc_g*bns

// ---------------- prep ----------------
__global__ void prep_transpose(
    const float* __restrict__ mlp1_W,
    const float* __restrict__ lse1_W,
    const float* __restrict__ lse2_W,
    const float* __restrict__ p1c1, const float* __restrict__ p1c2, const float* __restrict__ p1wm,
    const float* __restrict__ p2c1, const float* __restrict__ p2c2, const float* __restrict__ p2wm,
    const float* __restrict__ mlp2_W, const float* __restrict__ sc_W,
    const float* __restrict__ sc_g)
{
    const float bns = rsqrtf(1.0f + 1e-5f);
    int t = threadIdx.x;
    switch (blockIdx.x) {
        case 0:
            for (int i = t; i < 32*32; i += 256) g_mlp1Wt[(i%32)*32 + (i/32)] = mlp1_W[i];
            break;
        case 1:
            if (t < 32) {
                for (int d = 0; d < 3; d++) {
                    g_lse1We[d*32+t] = lse1_W[t*10+d]   + lse1_W[t*10+6+d];
                    g_lse1Wn[d*32+t] = lse1_W[t*10+3+d] - lse1_W[t*10+6+d];
                }
                g_lse1Wn[3*32+t] = lse1_W[t*10+9];
            }
            break;
        case 2:
            if (t < 32) {
                for (int d = 0; d < 3; d++) {
                    g_lse2We[d*32+t] = lse2_W[t*10+d]   + lse2_W[t*10+6+d];
                    g_lse2Wn[d*32+t] = lse2_W[t*10+3+d] - lse2_W[t*10+6+d];
                }
                g_lse2Wn[3*32+t] = lse2_W[t*10+9];
            }
            break;
        case 3:
            for (int i = t; i < 512; i += 256) {
                int j = i / 64, c = i % 64;
                g_p1c1p[((c>>2)*8 + j)*4 + (c&3)] = p1c1[i];
            }
            break;
        case 4:
            for (int i = t; i < 512; i += 256) {
                int r = i / 8, c = i % 8;
                g_p1c2p[((c>>2)*64 + r)*4 + (c&3)] = p1c2[i];
            }
            break;
        case 5:
            for (int i = t; i < 32*64; i += 256) g_p1wmt[(i%64)*32 + (i/64)] = p1wm[i];
            break;
        case 6:
            for (int i = t; i < 512; i += 256) {
                int j = i / 64, c = i % 64;
                g_p2c1p[((c>>2)*8 + j)*4 + (c&3)] = p2c1[i];
            }
            break;
        case 7:
            for (int i = t; i < 512; i += 256) {
                int r = i / 8, c = i % 8;
                g_p2c2p[((c>>2)*64 + r)*4 + (c&3)] = p2c2[i];
            }
            break;
        case 8:
            for (int i = t; i < 64*64; i += 256) g_p2wmt[(i%64)*64 + (i/64)] = p2wm[i];
            break;
        case 9:
            for (int i = t; i < 128*64; i += 256) g_mlp2t[(i%64)*128 + (i/64)] = mlp2_W[i];
            break;
        case 10:
            for (int i = t; i < 128*32; i += 256) {
                int oc = i / 32, d = i % 32;
                g_scWt[d*128 + oc] = sc_W[i] * sc_g[oc] * bns;
            }
            break;
        default: break;
    }
}

// ---------------- features (B,C,N) -> (B*N, C) ----------------
__global__ void feat_transpose(const float* __restrict__ f) {
    int gid = blockIdx.x * blockDim.x + threadIdx.x;
    if (gid >= BB*NN*CIN) return;
    int c = gid & 31;
    int p = gid >> 5;
    int b = p / NN, n = p % NN;
    g_feat_t[gid] = f[((size_t)b*CIN + c)*NN + n];
}

// ---------------- KNN: 4 queries per warp ----------------
#define KTILE 2048

__device__ __forceinline__ void insert_pass(unsigned m, float d2, int jc,
                                            float& lv, int& li, float& tau, int lane) {
    while (m) {
        int src = __ffs(m) - 1;
        m &= m - 1;
        float v  = __shfl_sync(FULLW, d2, src);
        int   vj = __shfl_sync(FULLW, jc, src);
        if (v < tau) {
            unsigned le = __ballot_sync(FULLW, (lane < KNN) && (lv <= v));
            int pos = __popc(le);
            float upv = __shfl_up_sync(FULLW, lv, 1);
            int   upi = __shfl_up_sync(FULLW, li, 1);
            if (lane == pos)                   { lv = v;   li = vj;  }
            else if (lane > pos && lane < KNN) { lv = upv; li = upi; }
            tau = __shfl_sync(FULLW, lv, KNN-1);
        }
    }
}

__global__ void __launch_bounds__(256) knn_kernel(const float* __restrict__ coords) {
    __shared__ float4 sc[KTILE];
    int b = blockIdx.y;
    int warp = threadIdx.x >> 5, lane = threadIdx.x & 31;
    int qb = (blockIdx.x * 8 + warp) * 4;
    const float* cb = coords + (size_t)b*NN*3;
    float qx0 = cb[(qb+0)*3+0], qy0 = cb[(qb+0)*3+1], qz0 = cb[(qb+0)*3+2];
    float qx1 = cb[(qb+1)*3+0], qy1 = cb[(qb+1)*3+1], qz1 = cb[(qb+1)*3+2];
    float qx2 = cb[(qb+2)*3+0], qy2 = cb[(qb+2)*3+1], qz2 = cb[(qb+2)*3+2];
    float qx3 = cb[(qb+3)*3+0], qy3 = cb[(qb+3)*3+1], qz3 = cb[(qb+3)*3+2];

    float lv0 = 3.4e38f, lv1 = 3.4e38f, lv2 = 3.4e38f, lv3 = 3.4e38f;
    int   li0 = -1, li1 = -1, li2 = -1, li3 = -1;
    float tau0 = 3.4e38f, tau1 = 3.4e38f, tau2 = 3.4e38f, tau3 = 3.4e38f;

    for (int t0 = 0; t0 < NN; t0 += KTILE) {
        __syncthreads();
        for (int u = threadIdx.x; u < KTILE; u += 256) {
            int j = t0 + u;
            float x = cb[j*3+0], y = cb[j*3+1], z = cb[j*3+2];
            sc[u] = make_float4(-2.0f*x, -2.0f*y, -2.0f*z, x*x + y*y + z*z);
        }
        __syncthreads();

        for (int u = 0; u < KTILE; u += 32) {
            float4 c = sc[u + lane];
            int jc = t0 + u + lane;
            float d20 = fmaf(qx0, c.x, fmaf(qy0, c.y, fmaf(qz0, c.z, c.w)));
            float d21 = fmaf(qx1, c.x, fmaf(qy1, c.y, fmaf(qz1, c.z, c.w)));
            float d22 = fmaf(qx2, c.x, fmaf(qy2, c.y, fmaf(qz2, c.z, c.w)));
            float d23 = fmaf(qx3, c.x, fmaf(qy3, c.y, fmaf(qz3, c.z, c.w)));
            unsigned m0 = __ballot_sync(FULLW, d20 < tau0);
            insert_pass(m0, d20, jc, lv0, li0, tau0, lane);
            unsigned m1 = __ballot_sync(FULLW, d21 < tau1);
            insert_pass(m1, d21, jc, lv1, li1, tau1, lane);
            unsigned m2 = __ballot_sync(FULLW, d22 < tau2);
            insert_pass(m2, d22, jc, lv2, li2, tau2, lane);
            unsigned m3 = __ballot_sync(FULLW, d23 < tau3);
            insert_pass(m3, d23, jc, lv3, li3, tau3, lane);
        }
    }
    if (lane < KNN) {
        g_idx[((size_t)b*NN + qb+0)*KNN + lane] = li0;
        g_idx[((size_t)b*NN + qb+1)*KNN + lane] = li1;
        g_idx[((size_t)b*NN + qb+2)*KNN + lane] = li2;
        g_idx[((size_t)b*NN + qb+3)*KNN + lane] = li3;
    }
}

// ---------------- fused per-point pipeline (8 points per 256-thread block) ----------------
__device__ __forceinline__ float sigmoidf_(float x) { return 1.0f / (1.0f + expf(-x)); }

// shared arena (reused across stages)
struct SArena {
    float4 nb[8][16];       // (nx,ny,nz,dist) per point per k
    float  A[8][64];
    float  M[8][64];
    float  Hs[8][8];
    float  Sp[8][16];
    float  Fe8[32*8];       // feat [d][p]
    float  F8[64*8];        // pooled-mlp input [j][p]
    float  Out8[64*8];      // stage output [oc][p]
    float  Part[4096];      // partials (pooled: [w][oc][p]; final: [slice][oc][p])
};

template<int NOUT>
__device__ __forceinline__ void stage(
    SArena* s, float featv, float cx, float cy, float cz,
    const float* __restrict__ We, const float* __restrict__ Wn,
    const float* __restrict__ bl, const float* __restrict__ gl, const float* __restrict__ btl,
    const float* __restrict__ c1p, const float* __restrict__ c2p,
    const float* __restrict__ Ws,
    const float* __restrict__ Wmt, const float* __restrict__ bm,
    const float* __restrict__ gm,  const float* __restrict__ btm,
    int lane, int warp, int tid)
{
    const float bns = rsqrtf(1.0f + 1e-5f);
    // ---- enc: e[k] = relu(bn(base + Wn·(nb,dist))) ----
    float we0 = We[0*32+lane], we1 = We[1*32+lane], we2 = We[2*32+lane];
    float wn0 = Wn[0*32+lane], wn1 = Wn[1*32+lane], wn2 = Wn[2*32+lane], wn3 = Wn[3*32+lane];
    float scl = gl[lane]*bns, shb = btl[lane];
    float base = bl[lane];
    base = fmaf(we0, cx, fmaf(we1, cy, fmaf(we2, cz, base)));

    float e[16];
    float avg = 0.f, mx = -3.4e38f;
#pragma unroll
    for (int k = 0; k < 16; k++) {
        float4 nb = s->nb[warp][k];
        float v = fmaf(wn0, nb.x, fmaf(wn1, nb.y, fmaf(wn2, nb.z, fmaf(wn3, nb.w, base))));
        v = fmaxf(scl*v + shb, 0.f);
        e[k] = v;
        avg += v;
        mx = fmaxf(mx, v);
    }
    avg *= 0.0625f;
    s->A[warp][lane] = avg; s->A[warp][32 + lane] = featv;
    s->M[warp][lane] = mx;  s->M[warp][32 + lane] = featv;
    __syncwarp();

    // ---- channel attention hidden: lane = (chalf, srcbit, j) ----
    {
        int j = lane & 7;
        int srcbit = (lane >> 3) & 1;
        int chalf = lane >> 4;
        const float* S = srcbit ? s->M[warp] : s->A[warp];
        float h = 0.f;
#pragma unroll
        for (int cq = 0; cq < 8; cq++) {
            int quad = chalf*8 + cq;
            float4 w4 = *reinterpret_cast<const float4*>(&c1p[(quad*8 + j)*4]);
            float4 a4 = *reinterpret_cast<const float4*>(&S[chalf*32 + cq*4]);
            h = fmaf(w4.x, a4.x, fmaf(w4.y, a4.y, fmaf(w4.z, a4.z, fmaf(w4.w, a4.w, h))));
        }
        h += __shfl_xor_sync(FULLW, h, 16);      // combine c-halves
        float h2 = fmaxf(h, 0.f);                // relu per branch
        float hsv = h2 + __shfl_xor_sync(FULLW, h2, 8);  // avg-branch + max-branch
        if (lane < 8) s->Hs[warp][lane] = hsv;
    }
    __syncwarp();

    // ---- ch = sigmoid(Wc2 @ hs) ----
    float4 hs0 = *reinterpret_cast<const float4*>(&s->Hs[warp][0]);
    float4 hs1 = *reinterpret_cast<const float4*>(&s->Hs[warp][4]);
    float a, b2;
    {
        float4 w0 = *reinterpret_cast<const float4*>(&c2p[lane*4]);
        float4 w1 = *reinterpret_cast<const float4*>(&c2p[(64 + lane)*4]);
        a = w0.x*hs0.x + w0.y*hs0.y + w0.z*hs0.z + w0.w*hs0.w
          + w1.x*hs1.x + w1.y*hs1.y + w1.z*hs1.z + w1.w*hs1.w;
        float4 v0 = *reinterpret_cast<const float4*>(&c2p[(32 + lane)*4]);
        float4 v1 = *reinterpret_cast<const float4*>(&c2p[(96 + lane)*4]);
        b2 = v0.x*hs0.x + v0.y*hs0.y + v0.z*hs0.z + v0.w*hs0.w
           + v1.x*hs1.x + v1.y*hs1.y + v1.z*hs1.z + v1.w*hs1.w;
    }
    float chA = sigmoidf_(a), chB = sigmoidf_(b2);
    float xf = featv * chB;

    // ---- spatial attention: butterfly reduce-scatter ----
    float vs[16], vm[16];
#pragma unroll
    for (int k = 0; k < 16; k++) {
        float ek = e[k] * chA;
        e[k] = ek;
        vs[k] = ek + xf;
        vm[k] = fmaxf(ek, xf);
    }
    {
        bool up = (lane & 16);
#pragma unroll
        for (int i = 0; i < 8; i++) {
            float ss = up ? vs[i] : vs[i+8];
            float ks = up ? vs[i+8] : vs[i];
            vs[i] = ks + __shfl_xor_sync(FULLW, ss, 16);
            float sm2 = up ? vm[i] : vm[i+8];
            float km = up ? vm[i+8] : vm[i];
            vm[i] = fmaxf(km, __shfl_xor_sync(FULLW, sm2, 16));
        }
    }
    {
        bool up = (lane & 8);
#pragma unroll
        for (int i = 0; i < 4; i++) {
            float ss = up ? vs[i] : vs[i+4];
            float ks = up ? vs[i+4] : vs[i];
            vs[i] = ks + __shfl_xor_sync(FULLW, ss, 8);
            float sm2 = up ? vm[i] : vm[i+4];
            float km = up ? vm[i+4] : vm[i];
            vm[i] = fmaxf(km, __shfl_xor_sync(FULLW, sm2, 8));
        }
    }
    {
        bool up = (lane & 4);
#pragma unroll
        for (int i = 0; i < 2; i++) {
            float ss = up ? vs[i] : vs[i+2];
            float ks = up ? vs[i+2] : vs[i];
            vs[i] = ks + __shfl_xor_sync(FULLW, ss, 4);
            float sm2 = up ? vm[i] : vm[i+2];
            float km = up ? vm[i+2] : vm[i];
            vm[i] = fmaxf(km, __shfl_xor_sync(FULLW, sm2, 4));
        }
    }
    {
        bool up = (lane & 2);
        float ss = up ? vs[0] : vs[1];
        float ks = up ? vs[1] : vs[0];
        vs[0] = ks + __shfl_xor_sync(FULLW, ss, 2);
        float sm2 = up ? vm[0] : vm[1];
        float km = up ? vm[1] : vm[0];
        vm[0] = fmaxf(km, __shfl_xor_sync(FULLW, sm2, 2));
    }
    vs[0] += __shfl_xor_sync(FULLW, vs[0], 1);
    vm[0] = fmaxf(vm[0], __shfl_xor_sync(FULLW, vm[0], 1));

    float ws0 = Ws[0], ws1 = Ws[1];
    float sp = sigmoidf_(ws0 * vs[0] * (1.0f/64.0f) + ws1 * vm[0]);
    int kL = (((lane>>4)&1)<<3) | (((lane>>3)&1)<<2) | (((lane>>2)&1)<<1) | ((lane>>1)&1);
    if (!(lane & 1)) s->Sp[warp][kL] = sp;
    float sps = sp;
#pragma unroll
    for (int off = 16; off > 0; off >>= 1) sps += __shfl_xor_sync(FULLW, sps, off);
    sps *= 0.5f;
    __syncwarp();

    float fA = 0.f;
#pragma unroll
    for (int k = 0; k < 16; k++) fA = fmaf(e[k], s->Sp[warp][k], fA);

    s->F8[lane*8 + warp]        = fA;
    s->F8[(32 + lane)*8 + warp] = xf * sps;
    __syncthreads();

    // ---- pooled mlp (block-cooperative over 8 points): warp owns j in [warp*8, +8) ----
    constexpr int G = NOUT/32;
    {
        float acc[G][8];
#pragma unroll
        for (int g = 0; g < G; g++)
#pragma unroll
            for (int p = 0; p < 8; p++) acc[g][p] = 0.f;
        int jb = warp * 8;
#pragma unroll
        for (int jj = 0; jj < 8; jj++) {
            int j = jb + jj;
            float4 a0 = *reinterpret_cast<const float4*>(&s->F8[j*8]);
            float4 a1 = *reinterpret_cast<const float4*>(&s->F8[j*8+4]);
#pragma unroll
            for (int g = 0; g < G; g++) {
                float wv = Wmt[j*NOUT + g*32 + lane];
                acc[g][0] = fmaf(wv, a0.x, acc[g][0]);
                acc[g][1] = fmaf(wv, a0.y, acc[g][1]);
                acc[g][2] = fmaf(wv, a0.z, acc[g][2]);
                acc[g][3] = fmaf(wv, a0.w, acc[g][3]);
                acc[g][4] = fmaf(wv, a1.x, acc[g][4]);
                acc[g][5] = fmaf(wv, a1.y, acc[g][5]);
                acc[g][6] = fmaf(wv, a1.z, acc[g][6]);
                acc[g][7] = fmaf(wv, a1.w, acc[g][7]);
            }
        }
#pragma unroll
        for (int g = 0; g < G; g++) {
            int bidx = (warp*NOUT + g*32 + lane)*8;
            *reinterpret_cast<float4*>(&s->Part[bidx])   = make_float4(acc[g][0], acc[g][1], acc[g][2], acc[g][3]);
            *reinterpret_cast<float4*>(&s->Part[bidx+4]) = make_float4(acc[g][4], acc[g][5], acc[g][6], acc[g][7]);
        }
    }
    __syncthreads();

    // ---- combine partials -> relu(bn(.)) -> Out8[oc][p] ----
#pragma unroll
    for (int g = 0; g < G; g++) {
        int idx = g*256 + tid;           // = oc*8 + p
        int oc = idx >> 3, pp = idx & 7;
        float sum = 0.f;
#pragma unroll
        for (int w = 0; w < 8; w++) sum += s->Part[(w*NOUT + oc)*8 + pp];
        sum += bm[oc];
        s->Out8[idx] = fmaxf(gm[oc]*bns*sum + btm[oc], 0.f);
    }
    __syncthreads();
}

__global__ void __launch_bounds__(256) fused_kernel(
    const float* __restrict__ coords,
    const float* __restrict__ mlp1_b,
    const float* __restrict__ lse1_b, const float* __restrict__ lse1_g, const float* __restrict__ lse1_bt,
    const float* __restrict__ p1_Ws,  const float* __restrict__ p1_bm,  const float* __restrict__ p1_g, const float* __restrict__ p1_bt,
    const float* __restrict__ lse2_b, const float* __restrict__ lse2_g, const float* __restrict__ lse2_bt,
    const float* __restrict__ p2_Ws,  const float* __restrict__ p2_bm,  const float* __restrict__ p2_g, const float* __restrict__ p2_bt,
    const float* __restrict__ mlp2_b,
    const float* __restrict__ sc_b, const float* __restrict__ sc_g, const float* __restrict__ sc_bt,
    float* __restrict__ out)
{
    __shared__ SArena s;

    int tid = threadIdx.x;
    int warp = tid >> 5, lane = tid & 31;
    int p = blockIdx.x * 8 + warp;
    int b = p >> 13, n = p & (NN - 1);

    s.Fe8[lane*8 + warp] = g_feat_t[p*CIN + lane];

    const float* cb = coords + ((size_t)b*NN + n)*3;
    float cx = cb[0], cy = cb[1], cz = cb[2];
    if (lane < 16) {
        int j = g_idx[p*KNN + lane];
        const float* nc = coords + ((size_t)b*NN + j)*3;
        float nx = nc[0], ny = nc[1], nz = nc[2];
        float dx = cx - nx, dy = cy - ny, dz = cz - nz;
        s.nb[warp][lane] = make_float4(nx, ny, nz, sqrtf(dx*dx + dy*dy + dz*dz));
    }
    __syncwarp();

    // x1 = leaky_relu(mlp1 @ feat + b, 0.2)
    float x1;
    {
        float acc = mlp1_b[lane];
#pragma unroll
        for (int d = 0; d < 32; d++) acc = fmaf(g_mlp1Wt[d*32 + lane], s.Fe8[d*8 + warp], acc);
        x1 = acc >= 0.f ? acc : 0.2f*acc;
    }

    stage<32>(&s, x1, cx, cy, cz, g_lse1We, g_lse1Wn, lse1_b, lse1_g, lse1_bt,
              g_p1c1p, g_p1c2p, p1_Ws, g_p1wmt, p1_bm, p1_g, p1_bt, lane, warp, tid);
    float o1 = s.Out8[lane*8 + warp];

    stage<64>(&s, o1, cx, cy, cz, g_lse2We, g_lse2Wn, lse2_b, lse2_g, lse2_bt,
              g_p2c1p, g_p2c2p, p2_Ws, g_p2wmt, p2_bm, p2_g, p2_bt, lane, warp, tid);

    // ---- final: leaky_relu(mlp2 @ o2 + mlp2_b + bn(sc_W @ feat + sc_b), 0.01) ----
    // thread = (oc-pair = tid&63, slice = tid>>6); sc weights pre-scaled by g*bns in prep
    {
        int slice = tid >> 6;
        int oc0 = (tid & 63) * 2;
        float acc0[8], acc1[8];
#pragma unroll
        for (int q = 0; q < 8; q++) { acc0[q] = 0.f; acc1[q] = 0.f; }
#pragma unroll
        for (int jj = 0; jj < 16; jj++) {
            int j = slice*16 + jj;
            float2 w2 = *reinterpret_cast<const float2*>(&g_mlp2t[j*128 + oc0]);
            float4 a0 = *reinterpret_cast<const float4*>(&s.Out8[j*8]);
            float4 a1 = *reinterpret_cast<const float4*>(&s.Out8[j*8+4]);
            acc0[0] = fmaf(w2.x, a0.x, acc0[0]); acc1[0] = fmaf(w2.y, a0.x, acc1[0]);
            acc0[1] = fmaf(w2.x, a0.y, acc0[1]); acc1[1] = fmaf(w2.y, a0.y, acc1[1]);
            acc0[2] = fmaf(w2.x, a0.z, acc0[2]); acc1[2] = fmaf(w2.y, a0.z, acc1[2]);
            acc0[3] = fmaf(w2.x, a0.w, acc0[3]); acc1[3] = fmaf(w2.y, a0.w, acc1[3]);
            acc0[4] = fmaf(w2.x, a1.x, acc0[4]); acc1[4] = fmaf(w2.y, a1.x, acc1[4]);
            acc0[5] = fmaf(w2.x, a1.y, acc0[5]); acc1[5] = fmaf(w2.y, a1.y, acc1[5]);
            acc0[6] = fmaf(w2.x, a1.z, acc0[6]); acc1[6] = fmaf(w2.y, a1.z, acc1[6]);
            acc0[7] = fmaf(w2.x, a1.w, acc0[7]); acc1[7] = fmaf(w2.y, a1.w, acc1[7]);
        }
#pragma unroll
        for (int dd = 0; dd < 8; dd++) {
            int d = slice*8 + dd;
            float2 w2 = *reinterpret_cast<const float2*>(&g_scWt[d*128 + oc0]);
            float4 f0 = *reinterpret_cast<const float4*>(&s.Fe8[d*8]);
            float4 f1 = *reinterpret_cast<const float4*>(&s.Fe8[d*8+4]);
            acc0[0] = fmaf(w2.x, f0.x, acc0[0]); acc1[0] = fmaf(w2.y, f0.x, acc1[0]);
            acc0[1] = fmaf(w2.x, f0.y, acc0[1]); acc1[1] = fmaf(w2.y, f0.y, acc1[1]);
            acc0[2] = fmaf(w2.x, f0.z, acc0[2]); acc1[2] = fmaf(w2.y, f0.z, acc1[2]);
            acc0[3] = fmaf(w2.x, f0.w, acc0[3]); acc1[3] = fmaf(w2.y, f0.w, acc1[3]);
            acc0[4] = fmaf(w2.x, f1.x, acc0[4]); acc1[4] = fmaf(w2.y, f1.x, acc1[4]);
            acc0[5] = fmaf(w2.x, f1.y, acc0[5]); acc1[5] = fmaf(w2.y, f1.y, acc1[5]);
            acc0[6] = fmaf(w2.x, f1.z, acc0[6]); acc1[6] = fmaf(w2.y, f1.z, acc1[6]);
            acc0[7] = fmaf(w2.x, f1.w, acc0[7]); acc1[7] = fmaf(w2.y, f1.w, acc1[7]);
        }
        int b0 = (slice*128 + oc0)*8;
        *reinterpret_cast<float4*>(&s.Part[b0])     = make_float4(acc0[0], acc0[1], acc0[2], acc0[3]);
        *reinterpret_cast<float4*>(&s.Part[b0+4])   = make_float4(acc0[4], acc0[5], acc0[6], acc0[7]);
        *reinterpret_cast<float4*>(&s.Part[b0+8])   = make_float4(acc1[0], acc1[1], acc1[2], acc1[3]);
        *reinterpret_cast<float4*>(&s.Part[b0+12])  = make_float4(acc1[4], acc1[5], acc1[6], acc1[7]);
    }
    __syncthreads();

    // combine 4 slices, add base, leaky, store
    {
        const float bns = rsqrtf(1.0f + 1e-5f);
        int oc = tid & 127;
        int ph = tid >> 7;           // 0 or 1 (points 0-3 / 4-7)
        float4 v = make_float4(0.f, 0.f, 0.f, 0.f);
#pragma unroll
        for (int sl = 0; sl < 4; sl++) {
            float4 t = *reinterpret_cast<const float4*>(&s.Part[(sl*128 + oc)*8 + ph*4]);
            v.x += t.x; v.y += t.y; v.z += t.z; v.w += t.w;
        }
        float basev = mlp2_b[oc] + sc_g[oc]*bns*sc_b[oc] + sc_bt[oc];
        v.x += basev; v.y += basev; v.z += basev; v.w += basev;
        v.x = v.x >= 0.f ? v.x : 0.01f*v.x;
        v.y = v.y >= 0.f ? v.y : 0.01f*v.y;
        v.z = v.z >= 0.f ? v.z : 0.01f*v.z;
        v.w = v.w >= 0.f ? v.w : 0.01f*v.w;

        int p0 = blockIdx.x * 8;
        int b0 = p0 >> 13, n0 = p0 & (NN - 1);
        *reinterpret_cast<float4*>(&out[((size_t)(b0*128 + oc))*NN + n0 + ph*4]) = v;
    }
}

// ---------------- launch ----------------
extern "C" void kernel_launch(void* const* d_in, const int* in_sizes, int n_in,
                              void* d_out, int out_size) {
    const float* coords   = (const float*)d_in[0];
    const float* features = (const float*)d_in[1];
    const float* mlp1_W = (const float*)d_in[2];
    const float* mlp1_b = (const float*)d_in[3];
    const float* lse1_W = (const float*)d_in[4];
    const float* lse1_b = (const float*)d_in[5];
    const float* lse1_g = (const float*)d_in[6];
    const float* lse1_bt = (const float*)d_in[7];
    const float* p1_Wc1 = (const float*)d_in[8];
    const float* p1_Wc2 = (const float*)d_in[9];
    const float* p1_Ws  = (const float*)d_in[10];
    const float* p1_Wm  = (const float*)d_in[11];
    const float* p1_bm  = (const float*)d_in[12];
    const float* p1_g   = (const float*)d_in[13];
    const float* p1_bt  = (const float*)d_in[14];
    const float* lse2_W = (const float*)d_in[15];
    const float* lse2_b = (const float*)d_in[16];
    const float* lse2_g = (const float*)d_in[17];
    const float* lse2_bt = (const float*)d_in[18];
    const float* p2_Wc1 = (const float*)d_in[19];
    const float* p2_Wc2 = (const float*)d_in[20];
    const float* p2_Ws  = (const float*)d_in[21];
    const float* p2_Wm  = (const float*)d_in[22];
    const float* p2_bm  = (const float*)d_in[23];
    const float* p2_g   = (const float*)d_in[24];
    const float* p2_bt  = (const float*)d_in[25];
    const float* mlp2_W = (const float*)d_in[26];
    const float* mlp2_b = (const float*)d_in[27];
    const float* sc_W   = (const float*)d_in[28];
    const float* sc_b   = (const float*)d_in[29];
    const float* sc_g   = (const float*)d_in[30];
    const float* sc_bt  = (const float*)d_in[31];
    float* out = (float*)d_out;

    prep_transpose<<<11, 256>>>(mlp1_W, lse1_W, lse2_W, p1_Wc1, p1_Wc2, p1_Wm,
                                p2_Wc1, p2_Wc2, p2_Wm, mlp2_W, sc_W, sc_g);
    feat_transpose<<<(BB*NN*CIN)/256, 256>>>(features);
    knn_kernel<<<dim3(NN/32, BB), 256>>>(coords);
    fused_kernel<<<(BB*NN)/8, 256>>>(coords, mlp1_b, lse1_b, lse1_g, lse1_bt,
                                     p1_Ws, p1_bm, p1_g, p1_bt,
                                     lse2_b, lse2_g, lse2_bt,
                                     p2_Ws, p2_bm, p2_g, p2_bt,
                                     mlp2_b, sc_b, sc_g, sc_bt, out);
}